// round 14
// baseline (speedup 1.0000x reference)
#include <cuda_runtime.h>
#include <cuda_fp16.h>
#include <cstdint>
#include <math.h>

// ---------------- problem constants ----------------
#define Bsz   4096
#define OBS   512
#define Tn    10
#define En    8
#define Wn    1024
#define Hn    12
#define XLD   (OBS + Tn)
#define EPSV  1e-8f

// ---------------- scratch (allocation-free) ----------------
__device__ __half g_obsh[Bsz * OBS];            // 4 MB
__device__ __half g_wh  [20971520];             // 40 MB: W0h | W1h | W2h
__device__ __half g_hwh [Tn * Wn * Hn];         // 240 KB: head_W fp16
__device__ __half g_h0  [Bsz * En * Wn];        // 64 MB
__device__ __half g_h1  [Bsz * En * Wn];        // 64 MB
__device__ __half g_eoh [Bsz * En * Wn];        // 64 MB (eo in fp16)
#define W0H_OFF 0
#define W1H_OFF (En * OBS * Wn)                 // 4194304
#define W2H_OFF (W1H_OFF + En * Wn * Wn)        // 12582912

// ---------------- helpers ----------------
__device__ __forceinline__ uint32_t smem_u32(const void* p) {
    uint32_t a;
    asm("{ .reg .u64 t; cvta.to.shared.u64 t, %1; cvt.u32.u64 %0, t; }" : "=r"(a) : "l"(p));
    return a;
}
__device__ __forceinline__ void cp16(uint32_t dst, const void* src) {
    asm volatile("cp.async.cg.shared.global [%0], [%1], 16;" :: "r"(dst), "l"(src));
}
__device__ __forceinline__ void cp_commit() { asm volatile("cp.async.commit_group;"); }
template<int N> __device__ __forceinline__ void cp_wait() {
    asm volatile("cp.async.wait_group %0;" :: "n"(N));
}
__device__ __forceinline__ void ldsm_x4(uint32_t* r, uint32_t addr) {
    asm volatile("ldmatrix.sync.aligned.m8n8.x4.shared.b16 {%0,%1,%2,%3}, [%4];"
                 : "=r"(r[0]), "=r"(r[1]), "=r"(r[2]), "=r"(r[3]) : "r"(addr));
}
__device__ __forceinline__ void ldsm_x4_trans(uint32_t* r, uint32_t addr) {
    asm volatile("ldmatrix.sync.aligned.m8n8.x4.trans.shared.b16 {%0,%1,%2,%3}, [%4];"
                 : "=r"(r[0]), "=r"(r[1]), "=r"(r[2]), "=r"(r[3]) : "r"(addr));
}
__device__ __forceinline__ void mma16816(float* c, const uint32_t* a, const uint32_t* b) {
    asm volatile(
        "mma.sync.aligned.m16n8k16.row.col.f32.f16.f16.f32 "
        "{%0,%1,%2,%3}, {%4,%5,%6,%7}, {%8,%9}, {%0,%1,%2,%3};"
        : "+f"(c[0]), "+f"(c[1]), "+f"(c[2]), "+f"(c[3])
        : "r"(a[0]), "r"(a[1]), "r"(a[2]), "r"(a[3]), "r"(b[0]), "r"(b[1]));
}

// ---------------------------------------------------------------------------
// fp32 -> fp16 conversion (grid-stride)
// ---------------------------------------------------------------------------
__global__ void cvt_half_kernel(const float* __restrict__ src, __half* __restrict__ dst, int n) {
    int i = (blockIdx.x * blockDim.x + threadIdx.x) * 2;
    const int stride = gridDim.x * blockDim.x * 2;
    for (; i < n; i += stride) {
        float2 v = *(const float2*)(src + i);
        *(__half2*)(dst + i) = __floats2half2_rn(v.x, v.y);
    }
}

// ---------------------------------------------------------------------------
// obs extraction + fp16 convert
// ---------------------------------------------------------------------------
__global__ void extract_obs_kernel(const float* __restrict__ x, __half* __restrict__ obs) {
    int b = blockIdx.x;
    const float* src = x + (size_t)b * XLD;
    __half* dst = obs + (size_t)b * OBS;
    int k = threadIdx.x * 2;
    *(__half2*)(dst + k) = __floats2half2_rn(src[k], src[k + 1]);
}

// ---------------------------------------------------------------------------
// FP16 mma.sync GEMM — R9-committed optimum (unchanged).
// ---------------------------------------------------------------------------
#define BM 128
#define BN 128
#define BK 32
#define NSTG 4
#define A_RB 80
#define B_RB 272
#define A_BYTES (BM * A_RB)
#define B_BYTES (BK * B_RB)
#define STAGE_BYTES (A_BYTES + B_BYTES)
#define GEMM_SMEM (NSTG * STAGE_BYTES)

__global__ __launch_bounds__(128, 2)
void gemm_fp16_kernel(const __half* __restrict__ A, const __half* __restrict__ W,
                      const float* __restrict__ bias, void* __restrict__ C,
                      int K, int lda, int a_eoff, int outHalf, int relu)
{
    extern __shared__ char sm[];

    const int tid  = threadIdx.x;
    const int wid  = tid >> 5;
    const int lane = tid & 31;
    const int gid  = lane >> 2;
    const int tig  = lane & 3;
    const int wm   = (wid & 1) * 64;
    const int wn   = (wid >> 1) * 64;

    const int e    = blockIdx.z;
    const int row0 = blockIdx.y * BM;
    const int n0   = blockIdx.x * BN;

    const __half* Ae = A + (size_t)e * a_eoff + (size_t)row0 * lda;
    const __half* We = W + (size_t)e * K * Wn + n0;
    const float*  be = bias + e * Wn + n0;

    const uint32_t smem_base = smem_u32(sm);

    auto load_A = [&](int c) {
        const uint32_t abase = smem_base + (c % NSTG) * STAGE_BYTES;
        const int k0 = c * BK;
#pragma unroll
        for (int i = 0; i < 4; i++) {
            int idx = tid + i * 128;
            int r = idx >> 2, ci = idx & 3;
            cp16(abase + (uint32_t)(r * A_RB + ci * 16),
                 Ae + (size_t)r * lda + k0 + ci * 8);
        }
    };
    auto load_B = [&](int c) {
        const uint32_t bbase = smem_base + (c % NSTG) * STAGE_BYTES + A_BYTES;
        const int k0 = c * BK;
#pragma unroll
        for (int i = 0; i < 4; i++) {
            int idx = tid + i * 128;
            int r = idx >> 4, ci = idx & 15;
            cp16(bbase + (uint32_t)(r * B_RB + ci * 16),
                 We + (size_t)(k0 + r) * Wn + ci * 8);
        }
    };

    float acc[4][8][4];
#pragma unroll
    for (int i = 0; i < 4; i++)
#pragma unroll
        for (int j = 0; j < 8; j++)
#pragma unroll
            for (int r = 0; r < 4; r++) acc[i][j][r] = 0.0f;

    const int nCh = K / BK;

    for (int c = 0; c < 3; c++) { load_A(c); load_B(c); cp_commit(); }

    const int a_row_l  = lane & 15;
    const int a_koff   = (lane >> 4) << 3;
    const int b_krow_l = lane & 15;
    const int b_noff   = (lane >> 4) << 3;

    for (int t = 0; t < nCh; t++) {
        cp_wait<2>();
        __syncthreads();

        const bool pf = (t + 3 < nCh);
        if (pf) load_A(t + 3);

        const uint32_t abase = smem_base + (t % NSTG) * STAGE_BYTES;
        const uint32_t bbase = abase + A_BYTES;

        // ---- kk = 0 ----
        {
            uint32_t af[4][4];
#pragma unroll
            for (int mt = 0; mt < 4; mt++)
                ldsm_x4(af[mt], abase + (uint32_t)((wm + mt * 16 + a_row_l) * A_RB + a_koff * 2));
            uint32_t bf[8][2];
#pragma unroll
            for (int np = 0; np < 4; np++) {
                uint32_t r[4];
                ldsm_x4_trans(r, bbase + (uint32_t)(b_krow_l * B_RB + (wn + np * 16 + b_noff) * 2));
                bf[np * 2][0]     = r[0]; bf[np * 2][1]     = r[1];
                bf[np * 2 + 1][0] = r[2]; bf[np * 2 + 1][1] = r[3];
            }
#pragma unroll
            for (int mt = 0; mt < 4; mt++)
#pragma unroll
                for (int nt = 0; nt < 8; nt++)
                    mma16816(acc[mt][nt], af[mt], bf[nt]);
        }

        if (pf) load_B(t + 3);
        cp_commit();

        // ---- kk = 1 ----
        {
            uint32_t af[4][4];
#pragma unroll
            for (int mt = 0; mt < 4; mt++)
                ldsm_x4(af[mt], abase + (uint32_t)((wm + mt * 16 + a_row_l) * A_RB + (16 + a_koff) * 2));
            uint32_t bf[8][2];
#pragma unroll
            for (int np = 0; np < 4; np++) {
                uint32_t r[4];
                ldsm_x4_trans(r, bbase + (uint32_t)((16 + b_krow_l) * B_RB + (wn + np * 16 + b_noff) * 2));
                bf[np * 2][0]     = r[0]; bf[np * 2][1]     = r[1];
                bf[np * 2 + 1][0] = r[2]; bf[np * 2 + 1][1] = r[3];
            }
#pragma unroll
            for (int mt = 0; mt < 4; mt++)
#pragma unroll
                for (int nt = 0; nt < 8; nt++)
                    mma16816(acc[mt][nt], af[mt], bf[nt]);
        }
    }

    // ---- epilogue ----
    if (outHalf) {
        __half* Ce = (__half*)C + (size_t)e * Wn;
#pragma unroll
        for (int mt = 0; mt < 4; mt++) {
#pragma unroll
            for (int nt = 0; nt < 8; nt++) {
                const int col = wn + nt * 8 + tig * 2;
                const float bx = be[col], by = be[col + 1];
                const int r0 = row0 + wm + mt * 16 + gid;
                float v0 = acc[mt][nt][0] + bx, v1 = acc[mt][nt][1] + by;
                float v2 = acc[mt][nt][2] + bx, v3 = acc[mt][nt][3] + by;
                if (relu) {
                    v0 = fmaxf(v0, 0.f); v1 = fmaxf(v1, 0.f);
                    v2 = fmaxf(v2, 0.f); v3 = fmaxf(v3, 0.f);
                }
                *(__half2*)(Ce + (size_t)r0 * (En * Wn) + n0 + col)       = __floats2half2_rn(v0, v1);
                *(__half2*)(Ce + (size_t)(r0 + 8) * (En * Wn) + n0 + col) = __floats2half2_rn(v2, v3);
            }
        }
    } else {
        float* Ce = (float*)C + (size_t)e * Wn;
#pragma unroll
        for (int mt = 0; mt < 4; mt++) {
#pragma unroll
            for (int nt = 0; nt < 8; nt++) {
                const int col = wn + nt * 8 + tig * 2;
                const float bx = be[col], by = be[col + 1];
                const int r0 = row0 + wm + mt * 16 + gid;
                float2 v0, v1;
                v0.x = acc[mt][nt][0] + bx; v0.y = acc[mt][nt][1] + by;
                v1.x = acc[mt][nt][2] + bx; v1.y = acc[mt][nt][3] + by;
                *(float2*)(Ce + (size_t)r0 * (En * Wn) + n0 + col)       = v0;
                *(float2*)(Ce + (size_t)(r0 + 8) * (En * Wn) + n0 + col) = v1;
            }
        }
    }
}

// ---------------------------------------------------------------------------
// Fused Gram-Schmidt + head (smem-resident, R12 skeleton) with:
//   - deferred normalization (sc[j] tracked; coeff = dot * sc_j^2)   [no scale sweeps]
//   - next step's dot pass fused into the update sweep               [1 sweep/step]
// ---------------------------------------------------------------------------
__global__ __launch_bounds__(256)
void gs_head_kernel(const float* __restrict__ x, const __half* __restrict__ eo,
                    const float* __restrict__ te_W, const __half* __restrict__ hwh,
                    const float* __restrict__ head_b, float* __restrict__ out)
{
    __shared__ float sv[En][Wn];        // 32 KB, unnormalized GS vectors
    __shared__ float redb[96];          // reduction scratch (<=9 values x 8 warps)
    __shared__ float s_te[En];
    __shared__ int   s_idx;

    const int b    = blockIdx.x;
    const int tid  = threadIdx.x;
    const int lane = tid & 31;
    const int w    = tid >> 5;

    // load eo row (fp16 -> fp32 smem)
    {
        const __half2* src = (const __half2*)(eo + (size_t)b * (En * Wn));
        for (int i = tid; i < En * Wn / 2; i += 256) {
            float2 v = __half22float2(src[i]);
            sv[0][i * 2]     = v.x;
            sv[0][i * 2 + 1] = v.y;
        }
    }
    if (tid < En) {
        float s = 0.0f;
        for (int t = 0; t < Tn; t++)
            s += x[(size_t)b * XLD + OBS + t] * te_W[t * En + tid];
        s_te[tid] = s;
    }
    if (tid == 0) {
        float best = -1e30f; int bi = 0;
        for (int t = 0; t < Tn; t++) {
            float v = x[(size_t)b * XLD + OBS + t];
            if (v > best) { best = v; bi = t; }
        }
        s_idx = bi;
    }
    __syncthreads();

    float sc[En];          // 1/(||w_j|| + eps), identical on all threads
    float dots[En];        // raw dots of v_{i} vs w_j, identical on all threads

    // ---- bootstrap: norm(v0) and dot(v1, v0) in one sweep ----
    {
        float nn = 0.0f, d0 = 0.0f;
        for (int k = tid; k < Wn; k += 256) {
            const float a = sv[0][k];
            nn += a * a;
            d0 += sv[1][k] * a;
        }
#pragma unroll
        for (int o = 16; o > 0; o >>= 1) {
            nn += __shfl_xor_sync(0xFFFFFFFFu, nn, o);
            d0 += __shfl_xor_sync(0xFFFFFFFFu, d0, o);
        }
        if (lane == 0) { redb[w] = nn; redb[8 + w] = d0; }
        __syncthreads();
        float sn = 0.0f, sd = 0.0f;
#pragma unroll
        for (int q = 0; q < 8; q++) { sn += redb[q]; sd += redb[8 + q]; }
        sc[0]   = 1.0f / (sqrtf(sn) + EPSV);
        dots[0] = sd;
        __syncthreads();                 // redb free for next writes
    }

    // ---- steps i = 1..7: one fused sweep each ----
    for (int i = 1; i < En; i++) {
        float c[En];
        for (int j = 0; j < i; j++) c[j] = dots[j] * sc[j] * sc[j];

        const int last = (i == En - 1);
        float nn = 0.0f;
        float nd[En];                    // dots of v_{i+1} vs w_j, j<=i
#pragma unroll
        for (int j = 0; j < En; j++) nd[j] = 0.0f;

        for (int k = tid; k < Wn; k += 256) {
            float wv = sv[i][k];
            float nv = last ? 0.0f : sv[i + 1][k];
            for (int j = 0; j < i; j++) {
                const float sj = sv[j][k];
                wv -= c[j] * sj;
                nd[j] += nv * sj;
            }
            sv[i][k] = wv;
            nn += wv * wv;
            nd[i] += nv * wv;            // vs freshly-updated w_i
        }

        // batched reduce: nn + (i+1) dots (skipped if last)
        const int nvals = last ? 1 : (i + 2);
#pragma unroll
        for (int o = 16; o > 0; o >>= 1) nn += __shfl_xor_sync(0xFFFFFFFFu, nn, o);
        if (lane == 0) redb[w] = nn;
        if (!last) {
            for (int j = 0; j <= i; j++) {
                float d = nd[j];
#pragma unroll
                for (int o = 16; o > 0; o >>= 1) d += __shfl_xor_sync(0xFFFFFFFFu, d, o);
                if (lane == 0) redb[(j + 1) * 8 + w] = d;
            }
        }
        __syncthreads();
        {
            float sn = 0.0f;
#pragma unroll
            for (int q = 0; q < 8; q++) sn += redb[q];
            sc[i] = 1.0f / (sqrtf(sn) + EPSV);
            if (!last) {
                for (int j = 0; j <= i; j++) {
                    float s = 0.0f;
#pragma unroll
                    for (int q = 0; q < 8; q++) s += redb[(j + 1) * 8 + q];
                    dots[j] = s;
                }
            }
            (void)nvals;
        }
        __syncthreads();                 // redb free for next iteration / head
    }

    // ---- feat = tanh(sum_e sv[e]*sc[e]*te[e]) ; head GEMV (fp16 weights) ----
    float g[En];
#pragma unroll
    for (int e = 0; e < En; e++) g[e] = sc[e] * s_te[e];

    const __half* hw = hwh + (size_t)s_idx * Wn * Hn;
    float hacc[Hn];
#pragma unroll
    for (int h = 0; h < Hn; h++) hacc[h] = 0.0f;

    for (int k = tid; k < Wn; k += 256) {
        float f = 0.0f;
#pragma unroll
        for (int e = 0; e < En; e++) f += sv[e][k] * g[e];
        f = tanhf(f);
        const __half2* hp = (const __half2*)(hw + (size_t)k * Hn);
#pragma unroll
        for (int h2 = 0; h2 < Hn / 2; h2++) {
            float2 wv = __half22float2(hp[h2]);
            hacc[h2 * 2]     += f * wv.x;
            hacc[h2 * 2 + 1] += f * wv.y;
        }
    }
#pragma unroll
    for (int h = 0; h < Hn; h++) {
        float p = hacc[h];
#pragma unroll
        for (int o = 16; o > 0; o >>= 1) p += __shfl_xor_sync(0xFFFFFFFFu, p, o);
        if (lane == 0) redb[h * 8 + w] = p;
    }
    __syncthreads();
    if (tid < Hn) {
        float s = 0.0f;
        for (int q = 0; q < 8; q++) s += redb[tid * 8 + q];
        out[(size_t)b * Hn + tid] = s + head_b[s_idx * Hn + tid];
    }
}

// ---------------------------------------------------------------------------
extern "C" void kernel_launch(void* const* d_in, const int* in_sizes, int n_in,
                              void* d_out, int out_size)
{
    const float* x      = (const float*)d_in[0];
    const float* te_W   = (const float*)d_in[1];
    const float* W0     = (const float*)d_in[2];
    const float* b0     = (const float*)d_in[3];
    const float* W1     = (const float*)d_in[4];
    const float* b1     = (const float*)d_in[5];
    const float* W2     = (const float*)d_in[6];
    const float* b2     = (const float*)d_in[7];
    const float* head_W = (const float*)d_in[8];
    const float* head_b = (const float*)d_in[9];
    float* out = (float*)d_out;

    __half *obsh, *wh, *hwh, *h0, *h1, *eoh;
    cudaGetSymbolAddress((void**)&obsh, g_obsh);
    cudaGetSymbolAddress((void**)&wh,   g_wh);
    cudaGetSymbolAddress((void**)&hwh,  g_hwh);
    cudaGetSymbolAddress((void**)&h0,   g_h0);
    cudaGetSymbolAddress((void**)&h1,   g_h1);
    cudaGetSymbolAddress((void**)&eoh,  g_eoh);

    cudaFuncSetAttribute(gemm_fp16_kernel, cudaFuncAttributeMaxDynamicSharedMemorySize, GEMM_SMEM);

    cvt_half_kernel<<<2048, 256>>>(W0, wh + W0H_OFF, En * OBS * Wn);
    cvt_half_kernel<<<4096, 256>>>(W1, wh + W1H_OFF, En * Wn * Wn);
    cvt_half_kernel<<<4096, 256>>>(W2, wh + W2H_OFF, En * Wn * Wn);
    cvt_half_kernel<<<240, 256>>>(head_W, hwh, Tn * Wn * Hn);
    extract_obs_kernel<<<Bsz, 256>>>(x, obsh);

    dim3 grid(Wn / BN, Bsz / BM, En);   // (8, 32, 8)
    gemm_fp16_kernel<<<grid, 128, GEMM_SMEM>>>(obsh, wh + W0H_OFF, b0, h0,  512,  OBS,     0,  1, 1);
    gemm_fp16_kernel<<<grid, 128, GEMM_SMEM>>>(h0,   wh + W1H_OFF, b1, h1,  1024, En * Wn, Wn, 1, 1);
    gemm_fp16_kernel<<<grid, 128, GEMM_SMEM>>>(h1,   wh + W2H_OFF, b2, eoh, 1024, En * Wn, Wn, 1, 0);

    gs_head_kernel<<<Bsz, 256>>>(x, eoh, te_W, hwh, head_b, out);
}

// round 16
// speedup vs baseline: 1.1558x; 1.1558x over previous
#include <cuda_runtime.h>
#include <cuda_fp16.h>
#include <cstdint>
#include <math.h>

// ---------------- problem constants ----------------
#define Bsz   4096
#define OBS   512
#define Tn    10
#define En    8
#define Wn    1024
#define Hn    12
#define XLD   (OBS + Tn)
#define EPSV  1e-8f

// ---------------- scratch (allocation-free) ----------------
__device__ __half g_obsh[Bsz * OBS];            // 4 MB
__device__ __half g_wh  [20971520];             // 40 MB: W0h | W1h | W2h
__device__ __half g_hwh [Tn * Wn * Hn];         // 240 KB: head_W fp16
__device__ __half g_h0  [Bsz * En * Wn];        // 64 MB
__device__ __half g_h1  [Bsz * En * Wn];        // 64 MB
__device__ __half g_eoh [Bsz * En * Wn];        // 64 MB (eo in fp16)
#define W0H_OFF 0
#define W1H_OFF (En * OBS * Wn)                 // 4194304
#define W2H_OFF (W1H_OFF + En * Wn * Wn)        // 12582912

// ---------------- helpers ----------------
__device__ __forceinline__ uint32_t smem_u32(const void* p) {
    uint32_t a;
    asm("{ .reg .u64 t; cvta.to.shared.u64 t, %1; cvt.u32.u64 %0, t; }" : "=r"(a) : "l"(p));
    return a;
}
__device__ __forceinline__ void cp16(uint32_t dst, const void* src) {
    asm volatile("cp.async.cg.shared.global [%0], [%1], 16;" :: "r"(dst), "l"(src));
}
__device__ __forceinline__ void cp_commit() { asm volatile("cp.async.commit_group;"); }
template<int N> __device__ __forceinline__ void cp_wait() {
    asm volatile("cp.async.wait_group %0;" :: "n"(N));
}
__device__ __forceinline__ void ldsm_x4(uint32_t* r, uint32_t addr) {
    asm volatile("ldmatrix.sync.aligned.m8n8.x4.shared.b16 {%0,%1,%2,%3}, [%4];"
                 : "=r"(r[0]), "=r"(r[1]), "=r"(r[2]), "=r"(r[3]) : "r"(addr));
}
__device__ __forceinline__ void ldsm_x4_trans(uint32_t* r, uint32_t addr) {
    asm volatile("ldmatrix.sync.aligned.m8n8.x4.trans.shared.b16 {%0,%1,%2,%3}, [%4];"
                 : "=r"(r[0]), "=r"(r[1]), "=r"(r[2]), "=r"(r[3]) : "r"(addr));
}
__device__ __forceinline__ void mma16816(float* c, const uint32_t* a, const uint32_t* b) {
    asm volatile(
        "mma.sync.aligned.m16n8k16.row.col.f32.f16.f16.f32 "
        "{%0,%1,%2,%3}, {%4,%5,%6,%7}, {%8,%9}, {%0,%1,%2,%3};"
        : "+f"(c[0]), "+f"(c[1]), "+f"(c[2]), "+f"(c[3])
        : "r"(a[0]), "r"(a[1]), "r"(a[2]), "r"(a[3]), "r"(b[0]), "r"(b[1]));
}

// ---------------------------------------------------------------------------
// fp32 -> fp16 conversion, vectorized: float4 load -> packed 8B store
// ---------------------------------------------------------------------------
__global__ void cvt_half_kernel(const float* __restrict__ src, __half* __restrict__ dst, int n) {
    int i = (blockIdx.x * blockDim.x + threadIdx.x) * 4;
    const int stride = gridDim.x * blockDim.x * 4;
    for (; i < n; i += stride) {
        float4 v = *(const float4*)(src + i);
        union { __half2 h[2]; unsigned long long u; } p;
        p.h[0] = __floats2half2_rn(v.x, v.y);
        p.h[1] = __floats2half2_rn(v.z, v.w);
        *(unsigned long long*)(dst + i) = p.u;
    }
}

// ---------------------------------------------------------------------------
// obs extraction + fp16 convert (unchanged from R12)
// ---------------------------------------------------------------------------
__global__ void extract_obs_kernel(const float* __restrict__ x, __half* __restrict__ obs) {
    int b = blockIdx.x;
    const float* src = x + (size_t)b * XLD;
    __half* dst = obs + (size_t)b * OBS;
    int k = threadIdx.x * 2;
    *(__half2*)(dst + k) = __floats2half2_rn(src[k], src[k + 1]);
}

// ---------------------------------------------------------------------------
// FP16 mma.sync GEMM — R9-committed optimum (unchanged).
// ---------------------------------------------------------------------------
#define BM 128
#define BN 128
#define BK 32
#define NSTG 4
#define A_RB 80
#define B_RB 272
#define A_BYTES (BM * A_RB)
#define B_BYTES (BK * B_RB)
#define STAGE_BYTES (A_BYTES + B_BYTES)
#define GEMM_SMEM (NSTG * STAGE_BYTES)

__global__ __launch_bounds__(128, 2)
void gemm_fp16_kernel(const __half* __restrict__ A, const __half* __restrict__ W,
                      const float* __restrict__ bias, void* __restrict__ C,
                      int K, int lda, int a_eoff, int outHalf, int relu)
{
    extern __shared__ char sm[];

    const int tid  = threadIdx.x;
    const int wid  = tid >> 5;
    const int lane = tid & 31;
    const int gid  = lane >> 2;
    const int tig  = lane & 3;
    const int wm   = (wid & 1) * 64;
    const int wn   = (wid >> 1) * 64;

    const int e    = blockIdx.z;
    const int row0 = blockIdx.y * BM;
    const int n0   = blockIdx.x * BN;

    const __half* Ae = A + (size_t)e * a_eoff + (size_t)row0 * lda;
    const __half* We = W + (size_t)e * K * Wn + n0;
    const float*  be = bias + e * Wn + n0;

    const uint32_t smem_base = smem_u32(sm);

    auto load_A = [&](int c) {
        const uint32_t abase = smem_base + (c % NSTG) * STAGE_BYTES;
        const int k0 = c * BK;
#pragma unroll
        for (int i = 0; i < 4; i++) {
            int idx = tid + i * 128;
            int r = idx >> 2, ci = idx & 3;
            cp16(abase + (uint32_t)(r * A_RB + ci * 16),
                 Ae + (size_t)r * lda + k0 + ci * 8);
        }
    };
    auto load_B = [&](int c) {
        const uint32_t bbase = smem_base + (c % NSTG) * STAGE_BYTES + A_BYTES;
        const int k0 = c * BK;
#pragma unroll
        for (int i = 0; i < 4; i++) {
            int idx = tid + i * 128;
            int r = idx >> 4, ci = idx & 15;
            cp16(bbase + (uint32_t)(r * B_RB + ci * 16),
                 We + (size_t)(k0 + r) * Wn + ci * 8);
        }
    };

    float acc[4][8][4];
#pragma unroll
    for (int i = 0; i < 4; i++)
#pragma unroll
        for (int j = 0; j < 8; j++)
#pragma unroll
            for (int r = 0; r < 4; r++) acc[i][j][r] = 0.0f;

    const int nCh = K / BK;

    for (int c = 0; c < 3; c++) { load_A(c); load_B(c); cp_commit(); }

    const int a_row_l  = lane & 15;
    const int a_koff   = (lane >> 4) << 3;
    const int b_krow_l = lane & 15;
    const int b_noff   = (lane >> 4) << 3;

    for (int t = 0; t < nCh; t++) {
        cp_wait<2>();
        __syncthreads();

        const bool pf = (t + 3 < nCh);
        if (pf) load_A(t + 3);

        const uint32_t abase = smem_base + (t % NSTG) * STAGE_BYTES;
        const uint32_t bbase = abase + A_BYTES;

        // ---- kk = 0 ----
        {
            uint32_t af[4][4];
#pragma unroll
            for (int mt = 0; mt < 4; mt++)
                ldsm_x4(af[mt], abase + (uint32_t)((wm + mt * 16 + a_row_l) * A_RB + a_koff * 2));
            uint32_t bf[8][2];
#pragma unroll
            for (int np = 0; np < 4; np++) {
                uint32_t r[4];
                ldsm_x4_trans(r, bbase + (uint32_t)(b_krow_l * B_RB + (wn + np * 16 + b_noff) * 2));
                bf[np * 2][0]     = r[0]; bf[np * 2][1]     = r[1];
                bf[np * 2 + 1][0] = r[2]; bf[np * 2 + 1][1] = r[3];
            }
#pragma unroll
            for (int mt = 0; mt < 4; mt++)
#pragma unroll
                for (int nt = 0; nt < 8; nt++)
                    mma16816(acc[mt][nt], af[mt], bf[nt]);
        }

        if (pf) load_B(t + 3);
        cp_commit();

        // ---- kk = 1 ----
        {
            uint32_t af[4][4];
#pragma unroll
            for (int mt = 0; mt < 4; mt++)
                ldsm_x4(af[mt], abase + (uint32_t)((wm + mt * 16 + a_row_l) * A_RB + (16 + a_koff) * 2));
            uint32_t bf[8][2];
#pragma unroll
            for (int np = 0; np < 4; np++) {
                uint32_t r[4];
                ldsm_x4_trans(r, bbase + (uint32_t)((16 + b_krow_l) * B_RB + (wn + np * 16 + b_noff) * 2));
                bf[np * 2][0]     = r[0]; bf[np * 2][1]     = r[1];
                bf[np * 2 + 1][0] = r[2]; bf[np * 2 + 1][1] = r[3];
            }
#pragma unroll
            for (int mt = 0; mt < 4; mt++)
#pragma unroll
                for (int nt = 0; nt < 8; nt++)
                    mma16816(acc[mt][nt], af[mt], bf[nt]);
        }
    }

    // ---- epilogue ----
    if (outHalf) {
        __half* Ce = (__half*)C + (size_t)e * Wn;
#pragma unroll
        for (int mt = 0; mt < 4; mt++) {
#pragma unroll
            for (int nt = 0; nt < 8; nt++) {
                const int col = wn + nt * 8 + tig * 2;
                const float bx = be[col], by = be[col + 1];
                const int r0 = row0 + wm + mt * 16 + gid;
                float v0 = acc[mt][nt][0] + bx, v1 = acc[mt][nt][1] + by;
                float v2 = acc[mt][nt][2] + bx, v3 = acc[mt][nt][3] + by;
                if (relu) {
                    v0 = fmaxf(v0, 0.f); v1 = fmaxf(v1, 0.f);
                    v2 = fmaxf(v2, 0.f); v3 = fmaxf(v3, 0.f);
                }
                *(__half2*)(Ce + (size_t)r0 * (En * Wn) + n0 + col)       = __floats2half2_rn(v0, v1);
                *(__half2*)(Ce + (size_t)(r0 + 8) * (En * Wn) + n0 + col) = __floats2half2_rn(v2, v3);
            }
        }
    } else {
        float* Ce = (float*)C + (size_t)e * Wn;
#pragma unroll
        for (int mt = 0; mt < 4; mt++) {
#pragma unroll
            for (int nt = 0; nt < 8; nt++) {
                const int col = wn + nt * 8 + tig * 2;
                const float bx = be[col], by = be[col + 1];
                const int r0 = row0 + wm + mt * 16 + gid;
                float2 v0, v1;
                v0.x = acc[mt][nt][0] + bx; v0.y = acc[mt][nt][1] + by;
                v1.x = acc[mt][nt][2] + bx; v1.y = acc[mt][nt][3] + by;
                *(float2*)(Ce + (size_t)r0 * (En * Wn) + n0 + col)       = v0;
                *(float2*)(Ce + (size_t)(r0 + 8) * (En * Wn) + n0 + col) = v1;
            }
        }
    }
}

// ---------------------------------------------------------------------------
// Fused Gram-Schmidt + tanh-combine + per-task head — exact R12 version.
// ---------------------------------------------------------------------------
__global__ __launch_bounds__(256)
void gs_head_kernel(const float* __restrict__ x, const __half* __restrict__ eo,
                    const float* __restrict__ te_W, const __half* __restrict__ hwh,
                    const float* __restrict__ head_b, float* __restrict__ out)
{
    __shared__ float sv[En][Wn];
    __shared__ float redb[96];
    __shared__ float s_coeff[En];
    __shared__ float s_scale;
    __shared__ float s_te[En];
    __shared__ int   s_idx;

    const int b    = blockIdx.x;
    const int tid  = threadIdx.x;
    const int lane = tid & 31;
    const int w    = tid >> 5;

    {
        const __half2* src = (const __half2*)(eo + (size_t)b * (En * Wn));
        for (int i = tid; i < En * Wn / 2; i += 256) {
            float2 v = __half22float2(src[i]);
            sv[0][i * 2]     = v.x;
            sv[0][i * 2 + 1] = v.y;
        }
    }
    if (tid < En) {
        float s = 0.0f;
        for (int t = 0; t < Tn; t++)
            s += x[(size_t)b * XLD + OBS + t] * te_W[t * En + tid];
        s_te[tid] = s;
    }
    if (tid == 0) {
        float best = -1e30f; int bi = 0;
        for (int t = 0; t < Tn; t++) {
            float v = x[(size_t)b * XLD + OBS + t];
            if (v > best) { best = v; bi = t; }
        }
        s_idx = bi;
    }
    __syncthreads();

    {
        float p = 0.0f;
        for (int k = tid; k < Wn; k += 256) { float v = sv[0][k]; p += v * v; }
#pragma unroll
        for (int o = 16; o > 0; o >>= 1) p += __shfl_xor_sync(0xFFFFFFFFu, p, o);
        if (lane == 0) redb[w] = p;
        __syncthreads();
        if (tid == 0) {
            float s = 0.0f;
            for (int q = 0; q < 8; q++) s += redb[q];
            s_scale = 1.0f / (sqrtf(s) + EPSV);
        }
        __syncthreads();
        const float inv = s_scale;
        for (int k = tid; k < Wn; k += 256) sv[0][k] *= inv;
        __syncthreads();
    }

    for (int i = 1; i < En; i++) {
        float part[En - 1];
#pragma unroll
        for (int j = 0; j < En - 1; j++) part[j] = 0.0f;
        for (int k = tid; k < Wn; k += 256) {
            const float v = sv[i][k];
            for (int j = 0; j < i; j++) part[j] += v * sv[j][k];
        }
        for (int j = 0; j < i; j++) {
            float p = part[j];
#pragma unroll
            for (int o = 16; o > 0; o >>= 1) p += __shfl_xor_sync(0xFFFFFFFFu, p, o);
            if (lane == 0) redb[j * 8 + w] = p;
        }
        __syncthreads();
        if (tid < i) {
            float s = 0.0f;
            for (int q = 0; q < 8; q++) s += redb[tid * 8 + q];
            s_coeff[tid] = s;
        }
        __syncthreads();

        float nn = 0.0f;
        for (int k = tid; k < Wn; k += 256) {
            float wv = sv[i][k];
            for (int j = 0; j < i; j++) wv -= s_coeff[j] * sv[j][k];
            sv[i][k] = wv;
            nn += wv * wv;
        }
#pragma unroll
        for (int o = 16; o > 0; o >>= 1) nn += __shfl_xor_sync(0xFFFFFFFFu, nn, o);
        if (lane == 0) redb[w] = nn;
        __syncthreads();
        if (tid == 0) {
            float s = 0.0f;
            for (int q = 0; q < 8; q++) s += redb[q];
            s_scale = 1.0f / (sqrtf(s) + EPSV);
        }
        __syncthreads();
        const float inv = s_scale;
        for (int k = tid; k < Wn; k += 256) sv[i][k] *= inv;
        __syncthreads();
    }

    const __half* hw = hwh + (size_t)s_idx * Wn * Hn;
    float hacc[Hn];
#pragma unroll
    for (int h = 0; h < Hn; h++) hacc[h] = 0.0f;

    for (int k = tid; k < Wn; k += 256) {
        float f = 0.0f;
#pragma unroll
        for (int e = 0; e < En; e++) f += sv[e][k] * s_te[e];
        f = tanhf(f);
        const __half2* hp = (const __half2*)(hw + (size_t)k * Hn);
#pragma unroll
        for (int h2 = 0; h2 < Hn / 2; h2++) {
            float2 wv = __half22float2(hp[h2]);
            hacc[h2 * 2]     += f * wv.x;
            hacc[h2 * 2 + 1] += f * wv.y;
        }
    }
#pragma unroll
    for (int h = 0; h < Hn; h++) {
        float p = hacc[h];
#pragma unroll
        for (int o = 16; o > 0; o >>= 1) p += __shfl_xor_sync(0xFFFFFFFFu, p, o);
        if (lane == 0) redb[h * 8 + w] = p;
    }
    __syncthreads();
    if (tid < Hn) {
        float s = 0.0f;
        for (int q = 0; q < 8; q++) s += redb[tid * 8 + q];
        out[(size_t)b * Hn + tid] = s + head_b[s_idx * Hn + tid];
    }
}

// ---------------------------------------------------------------------------
extern "C" void kernel_launch(void* const* d_in, const int* in_sizes, int n_in,
                              void* d_out, int out_size)
{
    const float* x      = (const float*)d_in[0];
    const float* te_W   = (const float*)d_in[1];
    const float* W0     = (const float*)d_in[2];
    const float* b0     = (const float*)d_in[3];
    const float* W1     = (const float*)d_in[4];
    const float* b1     = (const float*)d_in[5];
    const float* W2     = (const float*)d_in[6];
    const float* b2     = (const float*)d_in[7];
    const float* head_W = (const float*)d_in[8];
    const float* head_b = (const float*)d_in[9];
    float* out = (float*)d_out;

    __half *obsh, *wh, *hwh, *h0, *h1, *eoh;
    cudaGetSymbolAddress((void**)&obsh, g_obsh);
    cudaGetSymbolAddress((void**)&wh,   g_wh);
    cudaGetSymbolAddress((void**)&hwh,  g_hwh);
    cudaGetSymbolAddress((void**)&h0,   g_h0);
    cudaGetSymbolAddress((void**)&h1,   g_h1);
    cudaGetSymbolAddress((void**)&eoh,  g_eoh);

    cudaFuncSetAttribute(gemm_fp16_kernel, cudaFuncAttributeMaxDynamicSharedMemorySize, GEMM_SMEM);

    cvt_half_kernel<<<2048, 256>>>(W0, wh + W0H_OFF, En * OBS * Wn);
    cvt_half_kernel<<<4096, 256>>>(W1, wh + W1H_OFF, En * Wn * Wn);
    cvt_half_kernel<<<4096, 256>>>(W2, wh + W2H_OFF, En * Wn * Wn);
    cvt_half_kernel<<<120, 256>>>(head_W, hwh, Tn * Wn * Hn);
    extract_obs_kernel<<<Bsz, 256>>>(x, obsh);

    dim3 grid(Wn / BN, Bsz / BM, En);   // (8, 32, 8)
    gemm_fp16_kernel<<<grid, 128, GEMM_SMEM>>>(obsh, wh + W0H_OFF, b0, h0,  512,  OBS,     0,  1, 1);
    gemm_fp16_kernel<<<grid, 128, GEMM_SMEM>>>(h0,   wh + W1H_OFF, b1, h1,  1024, En * Wn, Wn, 1, 1);
    gemm_fp16_kernel<<<grid, 128, GEMM_SMEM>>>(h1,   wh + W2H_OFF, b2, eoh, 1024, En * Wn, Wn, 1, 0);

    gs_head_kernel<<<Bsz, 256>>>(x, eoh, te_W, hwh, head_b, out);
}

// round 17
// speedup vs baseline: 1.1773x; 1.0186x over previous
#include <cuda_runtime.h>
#include <cuda_fp16.h>
#include <cstdint>
#include <math.h>

// ---------------- problem constants ----------------
#define Bsz   4096
#define OBS   512
#define Tn    10
#define En    8
#define Wn    1024
#define Hn    12
#define XLD   (OBS + Tn)
#define EPSV  1e-8f

// ---------------- scratch (allocation-free) ----------------
__device__ __half g_obsh[Bsz * OBS];            // 4 MB
__device__ __half g_wh  [20971520];             // 40 MB: W0h | W1h | W2h
__device__ __half g_hwh [Tn * Wn * Hn];         // 240 KB: head_W fp16
__device__ __half g_h0  [Bsz * En * Wn];        // 64 MB
__device__ __half g_h1  [Bsz * En * Wn];        // 64 MB
__device__ __half g_eoh [Bsz * En * Wn];        // 64 MB (eo in fp16)
#define W0H_OFF 0
#define W1H_OFF (En * OBS * Wn)                 // 4194304
#define W2H_OFF (W1H_OFF + En * Wn * Wn)        // 12582912

// ---------------- helpers ----------------
__device__ __forceinline__ uint32_t smem_u32(const void* p) {
    uint32_t a;
    asm("{ .reg .u64 t; cvta.to.shared.u64 t, %1; cvt.u32.u64 %0, t; }" : "=r"(a) : "l"(p));
    return a;
}
__device__ __forceinline__ void cp16(uint32_t dst, const void* src) {
    asm volatile("cp.async.cg.shared.global [%0], [%1], 16;" :: "r"(dst), "l"(src));
}
__device__ __forceinline__ void cp_commit() { asm volatile("cp.async.commit_group;"); }
template<int N> __device__ __forceinline__ void cp_wait() {
    asm volatile("cp.async.wait_group %0;" :: "n"(N));
}
__device__ __forceinline__ void ldsm_x4(uint32_t* r, uint32_t addr) {
    asm volatile("ldmatrix.sync.aligned.m8n8.x4.shared.b16 {%0,%1,%2,%3}, [%4];"
                 : "=r"(r[0]), "=r"(r[1]), "=r"(r[2]), "=r"(r[3]) : "r"(addr));
}
__device__ __forceinline__ void ldsm_x4_trans(uint32_t* r, uint32_t addr) {
    asm volatile("ldmatrix.sync.aligned.m8n8.x4.trans.shared.b16 {%0,%1,%2,%3}, [%4];"
                 : "=r"(r[0]), "=r"(r[1]), "=r"(r[2]), "=r"(r[3]) : "r"(addr));
}
__device__ __forceinline__ void mma16816(float* c, const uint32_t* a, const uint32_t* b) {
    asm volatile(
        "mma.sync.aligned.m16n8k16.row.col.f32.f16.f16.f32 "
        "{%0,%1,%2,%3}, {%4,%5,%6,%7}, {%8,%9}, {%0,%1,%2,%3};"
        : "+f"(c[0]), "+f"(c[1]), "+f"(c[2]), "+f"(c[3])
        : "r"(a[0]), "r"(a[1]), "r"(a[2]), "r"(a[3]), "r"(b[0]), "r"(b[1]));
}

// ---------------------------------------------------------------------------
// fp32 -> fp16 conversion (grid-stride) — R12 version
// ---------------------------------------------------------------------------
__global__ void cvt_half_kernel(const float* __restrict__ src, __half* __restrict__ dst, int n) {
    int i = (blockIdx.x * blockDim.x + threadIdx.x) * 2;
    const int stride = gridDim.x * blockDim.x * 2;
    for (; i < n; i += stride) {
        float2 v = *(const float2*)(src + i);
        *(__half2*)(dst + i) = __floats2half2_rn(v.x, v.y);
    }
}

// ---------------------------------------------------------------------------
// obs extraction + fp16 convert
// ---------------------------------------------------------------------------
__global__ void extract_obs_kernel(const float* __restrict__ x, __half* __restrict__ obs) {
    int b = blockIdx.x;
    const float* src = x + (size_t)b * XLD;
    __half* dst = obs + (size_t)b * OBS;
    int k = threadIdx.x * 2;
    *(__half2*)(dst + k) = __floats2half2_rn(src[k], src[k + 1]);
}

// ---------------------------------------------------------------------------
// FP16 mma.sync GEMM — R9-committed optimum (unchanged).
// ---------------------------------------------------------------------------
#define BM 128
#define BN 128
#define BK 32
#define NSTG 4
#define A_RB 80
#define B_RB 272
#define A_BYTES (BM * A_RB)
#define B_BYTES (BK * B_RB)
#define STAGE_BYTES (A_BYTES + B_BYTES)
#define GEMM_SMEM (NSTG * STAGE_BYTES)

__global__ __launch_bounds__(128, 2)
void gemm_fp16_kernel(const __half* __restrict__ A, const __half* __restrict__ W,
                      const float* __restrict__ bias, void* __restrict__ C,
                      int K, int lda, int a_eoff, int outHalf, int relu)
{
    extern __shared__ char sm[];

    const int tid  = threadIdx.x;
    const int wid  = tid >> 5;
    const int lane = tid & 31;
    const int gid  = lane >> 2;
    const int tig  = lane & 3;
    const int wm   = (wid & 1) * 64;
    const int wn   = (wid >> 1) * 64;

    const int e    = blockIdx.z;
    const int row0 = blockIdx.y * BM;
    const int n0   = blockIdx.x * BN;

    const __half* Ae = A + (size_t)e * a_eoff + (size_t)row0 * lda;
    const __half* We = W + (size_t)e * K * Wn + n0;
    const float*  be = bias + e * Wn + n0;

    const uint32_t smem_base = smem_u32(sm);

    auto load_A = [&](int c) {
        const uint32_t abase = smem_base + (c % NSTG) * STAGE_BYTES;
        const int k0 = c * BK;
#pragma unroll
        for (int i = 0; i < 4; i++) {
            int idx = tid + i * 128;
            int r = idx >> 2, ci = idx & 3;
            cp16(abase + (uint32_t)(r * A_RB + ci * 16),
                 Ae + (size_t)r * lda + k0 + ci * 8);
        }
    };
    auto load_B = [&](int c) {
        const uint32_t bbase = smem_base + (c % NSTG) * STAGE_BYTES + A_BYTES;
        const int k0 = c * BK;
#pragma unroll
        for (int i = 0; i < 4; i++) {
            int idx = tid + i * 128;
            int r = idx >> 4, ci = idx & 15;
            cp16(bbase + (uint32_t)(r * B_RB + ci * 16),
                 We + (size_t)(k0 + r) * Wn + ci * 8);
        }
    };

    float acc[4][8][4];
#pragma unroll
    for (int i = 0; i < 4; i++)
#pragma unroll
        for (int j = 0; j < 8; j++)
#pragma unroll
            for (int r = 0; r < 4; r++) acc[i][j][r] = 0.0f;

    const int nCh = K / BK;

    for (int c = 0; c < 3; c++) { load_A(c); load_B(c); cp_commit(); }

    const int a_row_l  = lane & 15;
    const int a_koff   = (lane >> 4) << 3;
    const int b_krow_l = lane & 15;
    const int b_noff   = (lane >> 4) << 3;

    for (int t = 0; t < nCh; t++) {
        cp_wait<2>();
        __syncthreads();

        const bool pf = (t + 3 < nCh);
        if (pf) load_A(t + 3);

        const uint32_t abase = smem_base + (t % NSTG) * STAGE_BYTES;
        const uint32_t bbase = abase + A_BYTES;

        // ---- kk = 0 ----
        {
            uint32_t af[4][4];
#pragma unroll
            for (int mt = 0; mt < 4; mt++)
                ldsm_x4(af[mt], abase + (uint32_t)((wm + mt * 16 + a_row_l) * A_RB + a_koff * 2));
            uint32_t bf[8][2];
#pragma unroll
            for (int np = 0; np < 4; np++) {
                uint32_t r[4];
                ldsm_x4_trans(r, bbase + (uint32_t)(b_krow_l * B_RB + (wn + np * 16 + b_noff) * 2));
                bf[np * 2][0]     = r[0]; bf[np * 2][1]     = r[1];
                bf[np * 2 + 1][0] = r[2]; bf[np * 2 + 1][1] = r[3];
            }
#pragma unroll
            for (int mt = 0; mt < 4; mt++)
#pragma unroll
                for (int nt = 0; nt < 8; nt++)
                    mma16816(acc[mt][nt], af[mt], bf[nt]);
        }

        if (pf) load_B(t + 3);
        cp_commit();

        // ---- kk = 1 ----
        {
            uint32_t af[4][4];
#pragma unroll
            for (int mt = 0; mt < 4; mt++)
                ldsm_x4(af[mt], abase + (uint32_t)((wm + mt * 16 + a_row_l) * A_RB + (16 + a_koff) * 2));
            uint32_t bf[8][2];
#pragma unroll
            for (int np = 0; np < 4; np++) {
                uint32_t r[4];
                ldsm_x4_trans(r, bbase + (uint32_t)((16 + b_krow_l) * B_RB + (wn + np * 16 + b_noff) * 2));
                bf[np * 2][0]     = r[0]; bf[np * 2][1]     = r[1];
                bf[np * 2 + 1][0] = r[2]; bf[np * 2 + 1][1] = r[3];
            }
#pragma unroll
            for (int mt = 0; mt < 4; mt++)
#pragma unroll
                for (int nt = 0; nt < 8; nt++)
                    mma16816(acc[mt][nt], af[mt], bf[nt]);
        }
    }

    // ---- epilogue ----
    if (outHalf) {
        __half* Ce = (__half*)C + (size_t)e * Wn;
#pragma unroll
        for (int mt = 0; mt < 4; mt++) {
#pragma unroll
            for (int nt = 0; nt < 8; nt++) {
                const int col = wn + nt * 8 + tig * 2;
                const float bx = be[col], by = be[col + 1];
                const int r0 = row0 + wm + mt * 16 + gid;
                float v0 = acc[mt][nt][0] + bx, v1 = acc[mt][nt][1] + by;
                float v2 = acc[mt][nt][2] + bx, v3 = acc[mt][nt][3] + by;
                if (relu) {
                    v0 = fmaxf(v0, 0.f); v1 = fmaxf(v1, 0.f);
                    v2 = fmaxf(v2, 0.f); v3 = fmaxf(v3, 0.f);
                }
                *(__half2*)(Ce + (size_t)r0 * (En * Wn) + n0 + col)       = __floats2half2_rn(v0, v1);
                *(__half2*)(Ce + (size_t)(r0 + 8) * (En * Wn) + n0 + col) = __floats2half2_rn(v2, v3);
            }
        }
    } else {
        float* Ce = (float*)C + (size_t)e * Wn;
#pragma unroll
        for (int mt = 0; mt < 4; mt++) {
#pragma unroll
            for (int nt = 0; nt < 8; nt++) {
                const int col = wn + nt * 8 + tig * 2;
                const float bx = be[col], by = be[col + 1];
                const int r0 = row0 + wm + mt * 16 + gid;
                float2 v0, v1;
                v0.x = acc[mt][nt][0] + bx; v0.y = acc[mt][nt][1] + by;
                v1.x = acc[mt][nt][2] + bx; v1.y = acc[mt][nt][3] + by;
                *(float2*)(Ce + (size_t)r0 * (En * Wn) + n0 + col)       = v0;
                *(float2*)(Ce + (size_t)(r0 + 8) * (En * Wn) + n0 + col) = v1;
            }
        }
    }
}

// ---------------------------------------------------------------------------
// Gram-Schmidt step with COMPILE-TIME index I: all j-loops fully unrolled,
// part[]/c[] live in registers (no local memory). 4 barriers per step.
// ---------------------------------------------------------------------------
template<int I>
__device__ __forceinline__ void gs_step(float (*sv)[Wn], float* redb,
                                        int tid, int lane, int w)
{
    // dot pass: part[j] = <v_I, w_j> partials
    float part[I];
#pragma unroll
    for (int j = 0; j < I; j++) part[j] = 0.0f;
    for (int k = tid; k < Wn; k += 256) {
        const float v = sv[I][k];
#pragma unroll
        for (int j = 0; j < I; j++) part[j] += v * sv[j][k];
    }
#pragma unroll
    for (int j = 0; j < I; j++) {
        float p = part[j];
#pragma unroll
        for (int o = 16; o > 0; o >>= 1) p += __shfl_xor_sync(0xFFFFFFFFu, p, o);
        if (lane == 0) redb[j * 8 + w] = p;
    }
    __syncthreads();

    // coefficients: recomputed redundantly in registers by ALL threads
    float c[I];
#pragma unroll
    for (int j = 0; j < I; j++) {
        float s = 0.0f;
#pragma unroll
        for (int q = 0; q < 8; q++) s += redb[j * 8 + q];
        c[j] = s;
    }
    __syncthreads();          // all coeff reads done before redb reuse below

    // update pass + norm partial
    float nn = 0.0f;
    for (int k = tid; k < Wn; k += 256) {
        float wv = sv[I][k];
#pragma unroll
        for (int j = 0; j < I; j++) wv -= c[j] * sv[j][k];
        sv[I][k] = wv;
        nn += wv * wv;
    }
#pragma unroll
    for (int o = 16; o > 0; o >>= 1) nn += __shfl_xor_sync(0xFFFFFFFFu, nn, o);
    if (lane == 0) redb[w] = nn;
    __syncthreads();

    float s = 0.0f;
#pragma unroll
    for (int q = 0; q < 8; q++) s += redb[q];
    const float inv = 1.0f / (sqrtf(s) + EPSV);
    for (int k = tid; k < Wn; k += 256) sv[I][k] *= inv;
    __syncthreads();
}

// ---------------------------------------------------------------------------
// Fused Gram-Schmidt + tanh-combine + per-task head (templated GS steps).
// ---------------------------------------------------------------------------
__global__ __launch_bounds__(256)
void gs_head_kernel(const float* __restrict__ x, const __half* __restrict__ eo,
                    const float* __restrict__ te_W, const __half* __restrict__ hwh,
                    const float* __restrict__ head_b, float* __restrict__ out)
{
    __shared__ float sv[En][Wn];
    __shared__ float redb[96];
    __shared__ float s_te[En];
    __shared__ int   s_idx;

    const int b    = blockIdx.x;
    const int tid  = threadIdx.x;
    const int lane = tid & 31;
    const int w    = tid >> 5;

    {
        const __half2* src = (const __half2*)(eo + (size_t)b * (En * Wn));
        for (int i = tid; i < En * Wn / 2; i += 256) {
            float2 v = __half22float2(src[i]);
            sv[0][i * 2]     = v.x;
            sv[0][i * 2 + 1] = v.y;
        }
    }
    if (tid < En) {
        float s = 0.0f;
        for (int t = 0; t < Tn; t++)
            s += x[(size_t)b * XLD + OBS + t] * te_W[t * En + tid];
        s_te[tid] = s;
    }
    if (tid == 0) {
        float best = -1e30f; int bi = 0;
        for (int t = 0; t < Tn; t++) {
            float v = x[(size_t)b * XLD + OBS + t];
            if (v > best) { best = v; bi = t; }
        }
        s_idx = bi;
    }
    __syncthreads();

    // ---- vector 0 normalization ----
    {
        float p = 0.0f;
        for (int k = tid; k < Wn; k += 256) { float v = sv[0][k]; p += v * v; }
#pragma unroll
        for (int o = 16; o > 0; o >>= 1) p += __shfl_xor_sync(0xFFFFFFFFu, p, o);
        if (lane == 0) redb[w] = p;
        __syncthreads();
        float s = 0.0f;
#pragma unroll
        for (int q = 0; q < 8; q++) s += redb[q];
        const float inv = 1.0f / (sqrtf(s) + EPSV);
        for (int k = tid; k < Wn; k += 256) sv[0][k] *= inv;
        __syncthreads();
    }

    // ---- GS steps 1..7 (compile-time unrolled) ----
    gs_step<1>(sv, redb, tid, lane, w);
    gs_step<2>(sv, redb, tid, lane, w);
    gs_step<3>(sv, redb, tid, lane, w);
    gs_step<4>(sv, redb, tid, lane, w);
    gs_step<5>(sv, redb, tid, lane, w);
    gs_step<6>(sv, redb, tid, lane, w);
    gs_step<7>(sv, redb, tid, lane, w);

    // ---- feat = tanh(sum_e basis[e]*te[e]) ; head GEMV (fp16 weights) ----
    const __half* hw = hwh + (size_t)s_idx * Wn * Hn;
    float hacc[Hn];
#pragma unroll
    for (int h = 0; h < Hn; h++) hacc[h] = 0.0f;

    float te_r[En];
#pragma unroll
    for (int e = 0; e < En; e++) te_r[e] = s_te[e];

    for (int k = tid; k < Wn; k += 256) {
        float f = 0.0f;
#pragma unroll
        for (int e = 0; e < En; e++) f += sv[e][k] * te_r[e];
        f = tanhf(f);
        const __half2* hp = (const __half2*)(hw + (size_t)k * Hn);
#pragma unroll
        for (int h2 = 0; h2 < Hn / 2; h2++) {
            float2 wv = __half22float2(hp[h2]);
            hacc[h2 * 2]     += f * wv.x;
            hacc[h2 * 2 + 1] += f * wv.y;
        }
    }
#pragma unroll
    for (int h = 0; h < Hn; h++) {
        float p = hacc[h];
#pragma unroll
        for (int o = 16; o > 0; o >>= 1) p += __shfl_xor_sync(0xFFFFFFFFu, p, o);
        if (lane == 0) redb[h * 8 + w] = p;
    }
    __syncthreads();
    if (tid < Hn) {
        float s = 0.0f;
        for (int q = 0; q < 8; q++) s += redb[tid * 8 + q];
        out[(size_t)b * Hn + tid] = s + head_b[s_idx * Hn + tid];
    }
}

// ---------------------------------------------------------------------------
extern "C" void kernel_launch(void* const* d_in, const int* in_sizes, int n_in,
                              void* d_out, int out_size)
{
    const float* x      = (const float*)d_in[0];
    const float* te_W   = (const float*)d_in[1];
    const float* W0     = (const float*)d_in[2];
    const float* b0     = (const float*)d_in[3];
    const float* W1     = (const float*)d_in[4];
    const float* b1     = (const float*)d_in[5];
    const float* W2     = (const float*)d_in[6];
    const float* b2     = (const float*)d_in[7];
    const float* head_W = (const float*)d_in[8];
    const float* head_b = (const float*)d_in[9];
    float* out = (float*)d_out;

    __half *obsh, *wh, *hwh, *h0, *h1, *eoh;
    cudaGetSymbolAddress((void**)&obsh, g_obsh);
    cudaGetSymbolAddress((void**)&wh,   g_wh);
    cudaGetSymbolAddress((void**)&hwh,  g_hwh);
    cudaGetSymbolAddress((void**)&h0,   g_h0);
    cudaGetSymbolAddress((void**)&h1,   g_h1);
    cudaGetSymbolAddress((void**)&eoh,  g_eoh);

    cudaFuncSetAttribute(gemm_fp16_kernel, cudaFuncAttributeMaxDynamicSharedMemorySize, GEMM_SMEM);

    cvt_half_kernel<<<2048, 256>>>(W0, wh + W0H_OFF, En * OBS * Wn);
    cvt_half_kernel<<<4096, 256>>>(W1, wh + W1H_OFF, En * Wn * Wn);
    cvt_half_kernel<<<4096, 256>>>(W2, wh + W2H_OFF, En * Wn * Wn);
    cvt_half_kernel<<<240, 256>>>(head_W, hwh, Tn * Wn * Hn);
    extract_obs_kernel<<<Bsz, 256>>>(x, obsh);

    dim3 grid(Wn / BN, Bsz / BM, En);   // (8, 32, 8)
    gemm_fp16_kernel<<<grid, 128, GEMM_SMEM>>>(obsh, wh + W0H_OFF, b0, h0,  512,  OBS,     0,  1, 1);
    gemm_fp16_kernel<<<grid, 128, GEMM_SMEM>>>(h0,   wh + W1H_OFF, b1, h1,  1024, En * Wn, Wn, 1, 1);
    gemm_fp16_kernel<<<grid, 128, GEMM_SMEM>>>(h1,   wh + W2H_OFF, b2, eoh, 1024, En * Wn, Wn, 1, 0);

    gs_head_kernel<<<Bsz, 256>>>(x, eoh, te_W, hwh, head_b, out);
}